// round 2
// baseline (speedup 1.0000x reference)
#include <cuda_runtime.h>
#include <cstdint>

#define NB 8
#define NN 2048
#define NF 128

// ---- scratch (device globals: no runtime allocation allowed) ----
__device__ float g_d[NB * NN];            // d^-1/2 per (b,n)       64 KB
__device__ float g_y[NB * NN * NF];       // y' = d[m] * (x W^T)    8 MB
__device__ float g_Wt[NF * NF];           // W transposed           64 KB

// ----------------------------------------------------------------
// tf32 round-to-nearest conversion: b32 destination register (ptxas
// rejects an .f32 dst for cvt.rna.tf32.f32).
// ----------------------------------------------------------------
__device__ __forceinline__ float to_tf32(float x) {
    uint32_t u;
    asm("cvt.rna.tf32.f32 %0, %1;" : "=r"(u) : "f"(x));
    return __uint_as_float(u);
}

__device__ __forceinline__ void mma_tf32(float* c, const uint32_t* a, const uint32_t* b) {
    asm volatile(
        "mma.sync.aligned.m16n8k8.row.col.f32.tf32.tf32.f32 "
        "{%0,%1,%2,%3},{%4,%5,%6,%7},{%8,%9},{%0,%1,%2,%3};"
        : "+f"(c[0]), "+f"(c[1]), "+f"(c[2]), "+f"(c[3])
        : "r"(a[0]), "r"(a[1]), "r"(a[2]), "r"(a[3]), "r"(b[0]), "r"(b[1]));
}

// ----------------------------------------------------------------
// Kernel 1: degree -> d^-1/2.  One warp per row of adj (+self loop).
// ----------------------------------------------------------------
__global__ __launch_bounds__(256)
void degree_kernel(const float* __restrict__ adj) {
    int row = blockIdx.x * 8 + threadIdx.y;   // 0 .. NB*NN-1
    int lane = threadIdx.x;
    const float4* p = (const float4*)(adj + (size_t)row * NN);
    float s = 0.f;
    #pragma unroll 4
    for (int i = lane; i < NN / 4; i += 32) {
        float4 v = p[i];
        s += (v.x + v.y) + (v.z + v.w);
    }
    #pragma unroll
    for (int o = 16; o; o >>= 1) s += __shfl_xor_sync(0xFFFFFFFFu, s, o);
    if (lane == 0) g_d[row] = rsqrtf(s + 1.0f);
}

// ----------------------------------------------------------------
// Kernel 2: W^T  (g_Wt[f][o] = W[o][f])
// ----------------------------------------------------------------
__global__ void wt_kernel(const float* __restrict__ W) {
    int o = blockIdx.x, f = threadIdx.x;
    g_Wt[f * NF + o] = W[o * NF + f];
}

// ----------------------------------------------------------------
// Unified tf32 MMA GEMM.
//  MODE 0:  C[m,o] = d[m] * sum_f  x[m,f]   * Wt[f,o]     -> g_y
//           A = x (16384 x 128), K = 128
//  MODE 1:  C[n,o] = d[n]*( sum_m adj[b,n,m]*g_y[b,m,o] + g_y[b,n,o] ) + bias[o]
//           A = adj batch slice (2048 x 2048), K = 2048
// Block tile: 64 (rows) x 128 (cols), 8 warps (2x4), warp tile 32x32.
// ----------------------------------------------------------------
template <int MODE>
__global__ __launch_bounds__(256)
void gcn_mma_kernel(const float* __restrict__ Ag,
                    const float* __restrict__ bias,
                    float* __restrict__ outg) {
    constexpr int K   = (MODE == 0) ? NF : NN;
    constexpr int LDA = K;

    __shared__ float As[64][36];    // pad 36 -> conflict-free frag loads
    __shared__ float Bs[32][136];   // pad 136 -> conflict-free frag loads

    const int tid   = threadIdx.x;
    const int lane  = tid & 31;
    const int wid   = tid >> 5;
    const int wm    = wid >> 2;          // 0..1  (rows)
    const int wn    = wid & 3;           // 0..3  (cols)
    const int lr    = lane >> 2;         // 0..7
    const int lc    = lane & 3;          // 0..3

    const int batch = (MODE == 0) ? 0 : blockIdx.y;
    const int row0  = blockIdx.x * 64;

    const float* A = (MODE == 0)
        ? Ag + (size_t)row0 * NF
        : Ag + (size_t)batch * NN * NN + (size_t)row0 * NN;
    const float* Bp = (MODE == 0) ? g_Wt : g_y + (size_t)batch * NN * NF;

    float cacc[2][4][4];
    #pragma unroll
    for (int mi = 0; mi < 2; mi++)
        #pragma unroll
        for (int ni = 0; ni < 4; ni++)
            #pragma unroll
            for (int j = 0; j < 4; j++) cacc[mi][ni][j] = 0.f;

    for (int kt = 0; kt < K / 32; ++kt) {
        const int k0 = kt * 32;

        // ---- load A tile 64x32 (512 float4, 2 per thread) ----
        #pragma unroll
        for (int i = 0; i < 2; i++) {
            int q  = tid + i * 256;
            int r  = q >> 3;
            int c4 = (q & 7) * 4;
            float4 v = *(const float4*)(A + (size_t)r * LDA + k0 + c4);
            As[r][c4 + 0] = to_tf32(v.x);
            As[r][c4 + 1] = to_tf32(v.y);
            As[r][c4 + 2] = to_tf32(v.z);
            As[r][c4 + 3] = to_tf32(v.w);
        }
        // ---- load B tile 32x128 (1024 float4, 4 per thread) ----
        #pragma unroll
        for (int i = 0; i < 4; i++) {
            int q  = tid + i * 256;
            int r  = q >> 5;
            int c4 = (q & 31) * 4;
            float4 v = *(const float4*)(Bp + (size_t)(k0 + r) * NF + c4);
            Bs[r][c4 + 0] = to_tf32(v.x);
            Bs[r][c4 + 1] = to_tf32(v.y);
            Bs[r][c4 + 2] = to_tf32(v.z);
            Bs[r][c4 + 3] = to_tf32(v.w);
        }
        __syncthreads();

        #pragma unroll
        for (int ks = 0; ks < 4; ks++) {
            const int kk = ks * 8;
            uint32_t a[2][4], bq[4][2];
            #pragma unroll
            for (int mi = 0; mi < 2; mi++) {
                int ar = wm * 32 + mi * 16 + lr;
                a[mi][0] = __float_as_uint(As[ar][kk + lc]);
                a[mi][1] = __float_as_uint(As[ar + 8][kk + lc]);
                a[mi][2] = __float_as_uint(As[ar][kk + lc + 4]);
                a[mi][3] = __float_as_uint(As[ar + 8][kk + lc + 4]);
            }
            #pragma unroll
            for (int ni = 0; ni < 4; ni++) {
                int bc = wn * 32 + ni * 8 + lr;
                bq[ni][0] = __float_as_uint(Bs[kk + lc][bc]);
                bq[ni][1] = __float_as_uint(Bs[kk + lc + 4][bc]);
            }
            #pragma unroll
            for (int mi = 0; mi < 2; mi++)
                #pragma unroll
                for (int ni = 0; ni < 4; ni++)
                    mma_tf32(cacc[mi][ni], a[mi], bq[ni]);
        }
        __syncthreads();
    }

    // ---- epilogue ----
    #pragma unroll
    for (int mi = 0; mi < 2; mi++) {
        #pragma unroll
        for (int ri = 0; ri < 2; ri++) {
            const int lrow = wm * 32 + mi * 16 + lr + ri * 8;
            const int grow = row0 + lrow;
            if (MODE == 0) {
                const float dm = g_d[grow];
                #pragma unroll
                for (int ni = 0; ni < 4; ni++) {
                    int gcol = wn * 32 + ni * 8 + 2 * lc;
                    float2 v;
                    v.x = dm * cacc[mi][ni][ri * 2 + 0];
                    v.y = dm * cacc[mi][ni][ri * 2 + 1];
                    *(float2*)(g_y + (size_t)grow * NF + gcol) = v;
                }
            } else {
                const int gidx = batch * NN + grow;
                const float dn = g_d[gidx];
                #pragma unroll
                for (int ni = 0; ni < 4; ni++) {
                    int gcol = wn * 32 + ni * 8 + 2 * lc;
                    float2 yv = *(const float2*)(g_y + (size_t)gidx * NF + gcol);
                    float2 bv = *(const float2*)(bias + gcol);
                    float2 v;
                    v.x = dn * (cacc[mi][ni][ri * 2 + 0] + yv.x) + bv.x;
                    v.y = dn * (cacc[mi][ni][ri * 2 + 1] + yv.y) + bv.y;
                    *(float2*)(outg + (size_t)gidx * NF + gcol) = v;
                }
            }
        }
    }
}

// ----------------------------------------------------------------
extern "C" void kernel_launch(void* const* d_in, const int* in_sizes, int n_in,
                              void* d_out, int out_size) {
    const float *x = nullptr, *adj = nullptr, *W = nullptr, *bias = nullptr;
    for (int i = 0; i < n_in; i++) {
        int s = in_sizes[i];
        if (s == NB * NN * NN)      adj  = (const float*)d_in[i];
        else if (s == NB * NN * NF) x    = (const float*)d_in[i];
        else if (s == NF * NF)      W    = (const float*)d_in[i];
        else if (s == NF)           bias = (const float*)d_in[i];
    }
    float* out = (float*)d_out;

    // 1) degrees (one warp per row, 8 warps per block)
    degree_kernel<<<NB * NN / 8, dim3(32, 8)>>>(adj);
    // 2) W transpose
    wt_kernel<<<NF, NF>>>(W);
    // 3) y' = d[m] * (x W^T)   (M=16384, N=128, K=128)
    gcn_mma_kernel<0><<<dim3(NB * NN / 64, 1), 256>>>(x, nullptr, nullptr);
    // 4) out = d[n]*(adj @ y' + y'[n]) + bias   (per-batch M=2048, N=128, K=2048)
    gcn_mma_kernel<1><<<dim3(NN / 64, NB), 256>>>(adj, bias, out);
}

// round 4
// speedup vs baseline: 1.0145x; 1.0145x over previous
#include <cuda_runtime.h>
#include <cstdint>

#define NB 8
#define NN 2048
#define NF 128
#define KCH 32
#define NCHUNK (NN / KCH)   // 64

// ---- scratch (device globals; no runtime allocation allowed) ----
__device__ float g_d[NB * NN];                 // d^-1/2 per (b,n)
__device__ float g_y[(size_t)NB * NN * NF];    // tf32( d[m] * (x W^T)[m,f] )

// ----------------------------------------------------------------
__device__ __forceinline__ float to_tf32(float x) {
    uint32_t u;
    asm("cvt.rna.tf32.f32 %0, %1;" : "=r"(u) : "f"(x));
    return __uint_as_float(u);
}

__device__ __forceinline__ uint32_t smem_u32(const void* p) {
    uint32_t a;
    asm("{ .reg .u64 t; cvta.to.shared.u64 t, %1; cvt.u32.u64 %0, t; }"
        : "=r"(a) : "l"(p));
    return a;
}

__device__ __forceinline__ void mma_tf32(float* c, const uint32_t* a, const uint32_t* b) {
    asm volatile(
        "mma.sync.aligned.m16n8k8.row.col.f32.tf32.tf32.f32 "
        "{%0,%1,%2,%3},{%4,%5,%6,%7},{%8,%9},{%0,%1,%2,%3};"
        : "+f"(c[0]), "+f"(c[1]), "+f"(c[2]), "+f"(c[3])
        : "r"(a[0]), "r"(a[1]), "r"(a[2]), "r"(a[3]), "r"(b[0]), "r"(b[1]));
}

__device__ __forceinline__ void cp16(uint32_t dst, const void* src) {
    asm volatile("cp.async.cg.shared.global [%0], [%1], 16;"
                 :: "r"(dst), "l"(src) : "memory");
}

// ----------------------------------------------------------------
// Kernel 1: degree -> d^-1/2.  One warp per row of adj (+self loop).
// ----------------------------------------------------------------
__global__ __launch_bounds__(256)
void degree_kernel(const float* __restrict__ adj) {
    int row = blockIdx.x * 8 + threadIdx.y;
    int lane = threadIdx.x;
    const float4* p = (const float4*)(adj + (size_t)row * NN);
    float s = 0.f;
    #pragma unroll 4
    for (int i = lane; i < NN / 4; i += 32) {
        float4 v = p[i];
        s += (v.x + v.y) + (v.z + v.w);
    }
    #pragma unroll
    for (int o = 16; o; o >>= 1) s += __shfl_xor_sync(0xFFFFFFFFu, s, o);
    if (lane == 0) g_d[row] = rsqrtf(s + 1.0f);
}

// ----------------------------------------------------------------
// Kernel 2: g_y[m][f] = tf32( d[m] * sum_k x[m,k] * W[f,k] )
// CTA tile 64(m) x 128(f); A = x (row-major k), B = W (col-major over f: W[f][k]).
// 8 warps (wm 2 x wn 4), warp tile 32x32.
// ----------------------------------------------------------------
__global__ __launch_bounds__(256)
void xw_kernel(const float* __restrict__ x, const float* __restrict__ W) {
    __shared__ float As[64][36];    // x chunk  [m][k]
    __shared__ float Ws[128][36];   // W chunk  [f][k]

    const int tid  = threadIdx.x;
    const int lane = tid & 31;
    const int wid  = tid >> 5;
    const int wm   = wid >> 2;        // 0..1 over m
    const int wn   = wid & 3;         // 0..3 over f
    const int lr   = lane >> 2;
    const int lc   = lane & 3;
    const int m0   = blockIdx.x * 64;

    float cacc[2][4][4];
    #pragma unroll
    for (int mi = 0; mi < 2; mi++)
        #pragma unroll
        for (int ni = 0; ni < 4; ni++)
            #pragma unroll
            for (int j = 0; j < 4; j++) cacc[mi][ni][j] = 0.f;

    for (int kt = 0; kt < 4; ++kt) {
        const int k0 = kt * 32;
        // x chunk 64x32 (512 float4, 2/thread)
        #pragma unroll
        for (int i = 0; i < 2; i++) {
            int q = tid + i * 256;
            int r = q >> 3;
            int c4 = (q & 7) * 4;
            float4 v = *(const float4*)(x + (size_t)(m0 + r) * NF + k0 + c4);
            As[r][c4 + 0] = to_tf32(v.x);
            As[r][c4 + 1] = to_tf32(v.y);
            As[r][c4 + 2] = to_tf32(v.z);
            As[r][c4 + 3] = to_tf32(v.w);
        }
        // W chunk 128x32 (1024 float4, 4/thread)
        #pragma unroll
        for (int i = 0; i < 4; i++) {
            int q = tid + i * 256;
            int r = q >> 3;
            int c4 = (q & 7) * 4;
            float4 v = *(const float4*)(W + (size_t)r * NF + k0 + c4);
            Ws[r][c4 + 0] = to_tf32(v.x);
            Ws[r][c4 + 1] = to_tf32(v.y);
            Ws[r][c4 + 2] = to_tf32(v.z);
            Ws[r][c4 + 3] = to_tf32(v.w);
        }
        __syncthreads();

        #pragma unroll
        for (int ks = 0; ks < 4; ks++) {
            const int kk = ks * 8;
            uint32_t a[2][4], bq[4][2];
            #pragma unroll
            for (int mi = 0; mi < 2; mi++) {
                int ar = wm * 32 + mi * 16 + lr;
                a[mi][0] = __float_as_uint(As[ar][kk + lc]);
                a[mi][1] = __float_as_uint(As[ar + 8][kk + lc]);
                a[mi][2] = __float_as_uint(As[ar][kk + lc + 4]);
                a[mi][3] = __float_as_uint(As[ar + 8][kk + lc + 4]);
            }
            #pragma unroll
            for (int ni = 0; ni < 4; ni++) {
                int bc = wn * 32 + ni * 8 + lr;
                bq[ni][0] = __float_as_uint(Ws[bc][kk + lc]);
                bq[ni][1] = __float_as_uint(Ws[bc][kk + lc + 4]);
            }
            #pragma unroll
            for (int mi = 0; mi < 2; mi++)
                #pragma unroll
                for (int ni = 0; ni < 4; ni++)
                    mma_tf32(cacc[mi][ni], a[mi], bq[ni]);
        }
        __syncthreads();
    }

    // epilogue: g_y[m][f] = tf32(d[m] * acc)
    #pragma unroll
    for (int mi = 0; mi < 2; mi++) {
        #pragma unroll
        for (int ri = 0; ri < 2; ri++) {
            const int gm = m0 + wm * 32 + mi * 16 + lr + ri * 8;
            const float dm = g_d[gm];
            #pragma unroll
            for (int ni = 0; ni < 4; ni++) {
                int f = wn * 32 + ni * 8 + 2 * lc;
                float2 v;
                v.x = to_tf32(dm * cacc[mi][ni][ri * 2 + 0]);
                v.y = to_tf32(dm * cacc[mi][ni][ri * 2 + 1]);
                *(float2*)(g_y + (size_t)gm * NF + f) = v;
            }
        }
    }
}

// ----------------------------------------------------------------
// Kernel 3: out[b,n,f] = d[n] * sum_m (adj[b,n,m] + I[n,m]) * g_y[b,m,f] + bias[f]
// CTA tile 128(n) x 128(f), K = 2048 in 64 chunks of 32.
// 8 warps (wm 2 x wn 4), warp tile 64x32.  Double-buffered:
//   A (adj): LDG->regs (prefetch) -> cvt.rna + diag fold -> STS
//   B (g_y): cp.async.cg 16B straight to smem (already tf32)
// ----------------------------------------------------------------
#define A_STRIDE 36
#define B_STRIDE 136
#define A_STAGE (128 * A_STRIDE)            // floats
#define B_STAGE (32 * B_STRIDE)             // floats
#define SMEM_BYTES ((2 * A_STAGE + 2 * B_STAGE) * 4)   // 71680

__global__ __launch_bounds__(256, 1)
void adj_mma_kernel(const float* __restrict__ adj,
                    const float* __restrict__ bias,
                    float* __restrict__ out) {
    extern __shared__ float dsm[];
    float* Asm[2] = { dsm, dsm + A_STAGE };
    float* Bsm[2] = { dsm + 2 * A_STAGE, dsm + 2 * A_STAGE + B_STAGE };

    const int tid  = threadIdx.x;
    const int lane = tid & 31;
    const int wid  = tid >> 5;
    const int wm   = wid >> 2;        // 0..1 over n (64 rows each)
    const int wn   = wid & 3;         // 0..3 over f (32 cols each)
    const int lr   = lane >> 2;
    const int lc   = lane & 3;
    const int row0  = blockIdx.x * 128;
    const int batch = blockIdx.y;

    const float* Abase = adj + (size_t)batch * NN * NN + (size_t)row0 * NN;
    const float* Bbase = g_y + (size_t)batch * NN * NF;

    // A per-thread map: 4 rows (r0 + i*32), one float4 each
    const int ar0 = tid >> 3;
    const int ac4 = (tid & 7) * 4;
    // B per-thread map: 4 chunks of 16B
    float4 pa[4];

    auto ldgA = [&](int c) {
        const int k0 = c * KCH;
        #pragma unroll
        for (int i = 0; i < 4; i++)
            pa[i] = *(const float4*)(Abase + (size_t)(ar0 + i * 32) * NN + k0 + ac4);
    };
    auto stsA = [&](int c, int s) {
        const int k0 = c * KCH;
        #pragma unroll
        for (int i = 0; i < 4; i++) {
            int r = ar0 + i * 32;
            float4 v = pa[i];
            int diag = (row0 + r) - (k0 + ac4);
            if (diag >= 0 && diag < 4) ((float*)&v)[diag] += 1.0f;
            v.x = to_tf32(v.x); v.y = to_tf32(v.y);
            v.z = to_tf32(v.z); v.w = to_tf32(v.w);
            *(float4*)(Asm[s] + r * A_STRIDE + ac4) = v;
        }
    };
    auto cpB = [&](int c, int s) {
        const int k0 = c * KCH;
        #pragma unroll
        for (int i = 0; i < 4; i++) {
            int q = tid + i * 256;
            int r = q >> 5;
            int c4 = (q & 31) * 4;
            cp16(smem_u32(Bsm[s] + r * B_STRIDE + c4),
                 Bbase + (size_t)(k0 + r) * NF + c4);
        }
    };

    float cacc[4][4][4];
    #pragma unroll
    for (int mi = 0; mi < 4; mi++)
        #pragma unroll
        for (int ni = 0; ni < 4; ni++)
            #pragma unroll
            for (int j = 0; j < 4; j++) cacc[mi][ni][j] = 0.f;

    // ---- prologue ----
    ldgA(0);
    cpB(0, 0);
    asm volatile("cp.async.commit_group;" ::: "memory");
    stsA(0, 0);
    ldgA(1);
    cpB(1, 1);
    asm volatile("cp.async.commit_group;" ::: "memory");
    asm volatile("cp.async.wait_group 1;" ::: "memory");   // B(0) landed
    __syncthreads();

    for (int c = 0; c < NCHUNK; c++) {
        const int s = c & 1;
        const float* As = Asm[s];
        const float* Bs = Bsm[s];

        #pragma unroll
        for (int ks = 0; ks < 4; ks++) {
            const int kk = ks * 8;
            uint32_t a[4][4], bq[4][2];
            #pragma unroll
            for (int mi = 0; mi < 4; mi++) {
                int ar = wm * 64 + mi * 16 + lr;
                a[mi][0] = __float_as_uint(As[ar * A_STRIDE + kk + lc]);
                a[mi][1] = __float_as_uint(As[(ar + 8) * A_STRIDE + kk + lc]);
                a[mi][2] = __float_as_uint(As[ar * A_STRIDE + kk + lc + 4]);
                a[mi][3] = __float_as_uint(As[(ar + 8) * A_STRIDE + kk + lc + 4]);
            }
            #pragma unroll
            for (int ni = 0; ni < 4; ni++) {
                int bc = wn * 32 + ni * 8 + lr;
                bq[ni][0] = __float_as_uint(Bs[(kk + lc) * B_STRIDE + bc]);
                bq[ni][1] = __float_as_uint(Bs[(kk + lc + 4) * B_STRIDE + bc]);
            }
            #pragma unroll
            for (int mi = 0; mi < 4; mi++)
                #pragma unroll
                for (int ni = 0; ni < 4; ni++)
                    mma_tf32(cacc[mi][ni], a[mi], bq[ni]);
        }

        if (c + 1 < NCHUNK) {
            __syncthreads();                 // all warps done reading stage s
            stsA(c + 1, s ^ 1);              // regs hold A(c+1)
            if (c + 2 < NCHUNK) {
                ldgA(c + 2);
                cpB(c + 2, s);
                asm volatile("cp.async.commit_group;" ::: "memory");
                asm volatile("cp.async.wait_group 1;" ::: "memory");  // B(c+1) done
            } else {
                asm volatile("cp.async.wait_group 0;" ::: "memory");
            }
            __syncthreads();
        }
    }

    // ---- epilogue: out = d[n]*acc + bias ----
    #pragma unroll
    for (int mi = 0; mi < 4; mi++) {
        #pragma unroll
        for (int ri = 0; ri < 2; ri++) {
            const int grow = row0 + wm * 64 + mi * 16 + lr + ri * 8;
            const float dn = g_d[batch * NN + grow];
            float* po = out + ((size_t)(batch * NN + grow)) * NF;
            #pragma unroll
            for (int ni = 0; ni < 4; ni++) {
                int f = wn * 32 + ni * 8 + 2 * lc;
                float2 bv = *(const float2*)(bias + f);
                float2 v;
                v.x = dn * cacc[mi][ni][ri * 2 + 0] + bv.x;
                v.y = dn * cacc[mi][ni][ri * 2 + 1] + bv.y;
                *(float2*)(po + f) = v;
            }
        }
    }
}

// ----------------------------------------------------------------
extern "C" void kernel_launch(void* const* d_in, const int* in_sizes, int n_in,
                              void* d_out, int out_size) {
    const float *x = nullptr, *adj = nullptr, *W = nullptr, *bias = nullptr;
    for (int i = 0; i < n_in; i++) {
        int s = in_sizes[i];
        if (s == NB * NN * NN)      adj  = (const float*)d_in[i];
        else if (s == NB * NN * NF) x    = (const float*)d_in[i];
        else if (s == NF * NF)      W    = (const float*)d_in[i];
        else if (s == NF)           bias = (const float*)d_in[i];
    }
    float* out = (float*)d_out;

    cudaFuncSetAttribute(adj_mma_kernel,
                         cudaFuncAttributeMaxDynamicSharedMemorySize, SMEM_BYTES);

    degree_kernel<<<NB * NN / 8, dim3(32, 8)>>>(adj);
    xw_kernel<<<NB * NN / 64, 256>>>(x, W);
    adj_mma_kernel<<<dim3(NN / 128, NB), 256, SMEM_BYTES>>>(adj, bias, out);
}

// round 5
// speedup vs baseline: 1.2416x; 1.2238x over previous
#include <cuda_runtime.h>
#include <cuda_fp16.h>
#include <cstdint>

#define NB 8
#define NN 2048
#define NF 128
#define KCH 32
#define NCHUNK (NN / KCH)   // 64

// ---- scratch (device globals; no runtime allocation allowed) ----
__device__ float  g_d[NB * NN];                   // d^-1/2 per (b,n)
__device__ __half g_yt[(size_t)NB * NF * NN];     // fp16( d[m] * (x W^T)[m,f] ), [b][f][m]

// ----------------------------------------------------------------
__device__ __forceinline__ float to_tf32(float x) {
    uint32_t u;
    asm("cvt.rna.tf32.f32 %0, %1;" : "=r"(u) : "f"(x));
    return __uint_as_float(u);
}

__device__ __forceinline__ uint32_t smem_u32(const void* p) {
    uint32_t a;
    asm("{ .reg .u64 t; cvta.to.shared.u64 t, %1; cvt.u32.u64 %0, t; }"
        : "=r"(a) : "l"(p));
    return a;
}

__device__ __forceinline__ void mma_tf32(float* c, const uint32_t* a, const uint32_t* b) {
    asm volatile(
        "mma.sync.aligned.m16n8k8.row.col.f32.tf32.tf32.f32 "
        "{%0,%1,%2,%3},{%4,%5,%6,%7},{%8,%9},{%0,%1,%2,%3};"
        : "+f"(c[0]), "+f"(c[1]), "+f"(c[2]), "+f"(c[3])
        : "r"(a[0]), "r"(a[1]), "r"(a[2]), "r"(a[3]), "r"(b[0]), "r"(b[1]));
}

__device__ __forceinline__ void mma_f16(float* c, const uint32_t* a, const uint32_t* b) {
    asm volatile(
        "mma.sync.aligned.m16n8k16.row.col.f32.f16.f16.f32 "
        "{%0,%1,%2,%3},{%4,%5,%6,%7},{%8,%9},{%0,%1,%2,%3};"
        : "+f"(c[0]), "+f"(c[1]), "+f"(c[2]), "+f"(c[3])
        : "r"(a[0]), "r"(a[1]), "r"(a[2]), "r"(a[3]), "r"(b[0]), "r"(b[1]));
}

__device__ __forceinline__ void cp16(uint32_t dst, const void* src) {
    asm volatile("cp.async.cg.shared.global [%0], [%1], 16;"
                 :: "r"(dst), "l"(src) : "memory");
}

// ----------------------------------------------------------------
// Kernel 1: degree -> d^-1/2.  One warp per row of adj (+self loop).
// ----------------------------------------------------------------
__global__ __launch_bounds__(256)
void degree_kernel(const float* __restrict__ adj) {
    int row = blockIdx.x * 8 + threadIdx.y;
    int lane = threadIdx.x;
    const float4* p = (const float4*)(adj + (size_t)row * NN);
    float s = 0.f;
    #pragma unroll 4
    for (int i = lane; i < NN / 4; i += 32) {
        float4 v = p[i];
        s += (v.x + v.y) + (v.z + v.w);
    }
    #pragma unroll
    for (int o = 16; o; o >>= 1) s += __shfl_xor_sync(0xFFFFFFFFu, s, o);
    if (lane == 0) g_d[row] = rsqrtf(s + 1.0f);
}

// ----------------------------------------------------------------
// Kernel 2: g_yt[b][f][m] = fp16( d[m] * sum_k x[m,k] * W[f,k] )
// CTA tile 64(m) x 128(f), tf32 MMA internally.
// ----------------------------------------------------------------
__global__ __launch_bounds__(256)
void xw_kernel(const float* __restrict__ x, const float* __restrict__ W) {
    __shared__ float As[64][36];    // x chunk  [m][k]
    __shared__ float Ws[128][36];   // W chunk  [f][k]

    const int tid  = threadIdx.x;
    const int lane = tid & 31;
    const int wid  = tid >> 5;
    const int wm   = wid >> 2;        // 0..1 over m
    const int wn   = wid & 3;         // 0..3 over f
    const int lr   = lane >> 2;
    const int lc   = lane & 3;
    const int m0   = blockIdx.x * 64;

    float cacc[2][4][4];
    #pragma unroll
    for (int mi = 0; mi < 2; mi++)
        #pragma unroll
        for (int ni = 0; ni < 4; ni++)
            #pragma unroll
            for (int j = 0; j < 4; j++) cacc[mi][ni][j] = 0.f;

    for (int kt = 0; kt < 4; ++kt) {
        const int k0 = kt * 32;
        #pragma unroll
        for (int i = 0; i < 2; i++) {
            int q = tid + i * 256;
            int r = q >> 3;
            int c4 = (q & 7) * 4;
            float4 v = *(const float4*)(x + (size_t)(m0 + r) * NF + k0 + c4);
            As[r][c4 + 0] = to_tf32(v.x);
            As[r][c4 + 1] = to_tf32(v.y);
            As[r][c4 + 2] = to_tf32(v.z);
            As[r][c4 + 3] = to_tf32(v.w);
        }
        #pragma unroll
        for (int i = 0; i < 4; i++) {
            int q = tid + i * 256;
            int r = q >> 3;
            int c4 = (q & 7) * 4;
            float4 v = *(const float4*)(W + (size_t)r * NF + k0 + c4);
            Ws[r][c4 + 0] = to_tf32(v.x);
            Ws[r][c4 + 1] = to_tf32(v.y);
            Ws[r][c4 + 2] = to_tf32(v.z);
            Ws[r][c4 + 3] = to_tf32(v.w);
        }
        __syncthreads();

        #pragma unroll
        for (int ks = 0; ks < 4; ks++) {
            const int kk = ks * 8;
            uint32_t a[2][4], bq[4][2];
            #pragma unroll
            for (int mi = 0; mi < 2; mi++) {
                int ar = wm * 32 + mi * 16 + lr;
                a[mi][0] = __float_as_uint(As[ar][kk + lc]);
                a[mi][1] = __float_as_uint(As[ar + 8][kk + lc]);
                a[mi][2] = __float_as_uint(As[ar][kk + lc + 4]);
                a[mi][3] = __float_as_uint(As[ar + 8][kk + lc + 4]);
            }
            #pragma unroll
            for (int ni = 0; ni < 4; ni++) {
                int bc = wn * 32 + ni * 8 + lr;
                bq[ni][0] = __float_as_uint(Ws[bc][kk + lc]);
                bq[ni][1] = __float_as_uint(Ws[bc][kk + lc + 4]);
            }
            #pragma unroll
            for (int mi = 0; mi < 2; mi++)
                #pragma unroll
                for (int ni = 0; ni < 4; ni++)
                    mma_tf32(cacc[mi][ni], a[mi], bq[ni]);
        }
        __syncthreads();
    }

    // epilogue: g_yt[b][f][m] = fp16(d[m] * acc)
    #pragma unroll
    for (int mi = 0; mi < 2; mi++) {
        #pragma unroll
        for (int ri = 0; ri < 2; ri++) {
            const int gm   = m0 + wm * 32 + mi * 16 + lr + ri * 8;
            const int b    = gm >> 11;
            const int mloc = gm & (NN - 1);
            const float dm = g_d[gm];
            #pragma unroll
            for (int ni = 0; ni < 4; ni++) {
                int f = wn * 32 + ni * 8 + 2 * lc;
                g_yt[(size_t)(b * NF + f)     * NN + mloc] =
                    __float2half_rn(dm * cacc[mi][ni][ri * 2 + 0]);
                g_yt[(size_t)(b * NF + f + 1) * NN + mloc] =
                    __float2half_rn(dm * cacc[mi][ni][ri * 2 + 1]);
            }
        }
    }
}

// ----------------------------------------------------------------
// Kernel 3 (fp16 m16n8k16): out[b,n,f] = d[n]*sum_m (adj+I)[n,m]*y[m,f] + bias[f]
// CTA tile 128(n) x 128(f), K=2048 in 64 chunks of 32.
// 8 warps (wm 2 x wn 4), warp tile 64x32.  Double-buffered:
//   A (adj fp32): LDG->regs -> diag fold -> fp16 cvt -> STS
//   B (g_yt fp16): cp.async 16B straight to smem
// ----------------------------------------------------------------
#define A_STRIDE 40                          // halfs per row (80B, conflict-free)
#define B_STRIDE 40
#define A_STAGE (128 * A_STRIDE)             // halfs
#define B_STAGE (128 * B_STRIDE)             // halfs
#define SMEM_BYTES ((2 * A_STAGE + 2 * B_STAGE) * 2)   // 40960

__global__ __launch_bounds__(256, 1)
void adj_mma_kernel(const float* __restrict__ adj,
                    const float* __restrict__ bias,
                    float* __restrict__ out) {
    extern __shared__ __half hsm[];
    __half* Asm[2] = { hsm, hsm + A_STAGE };
    __half* Bsm[2] = { hsm + 2 * A_STAGE, hsm + 2 * A_STAGE + B_STAGE };

    const int tid  = threadIdx.x;
    const int lane = tid & 31;
    const int wid  = tid >> 5;
    const int wm   = wid >> 2;        // 0..1 over n (64 rows each)
    const int wn   = wid & 3;         // 0..3 over f (32 cols each)
    const int lr   = lane >> 2;       // 0..7
    const int lc   = lane & 3;        // 0..3
    const int row0  = blockIdx.x * 128;
    const int batch = blockIdx.y;

    const float*  Abase = adj + (size_t)batch * NN * NN + (size_t)row0 * NN;
    const __half* Bbase = g_yt + (size_t)batch * NF * NN;

    const int ar0 = tid >> 3;          // A row 0..31 (+i*32)
    const int ac4 = (tid & 7) * 4;     // A col (fp32 elems)
    float4 pa[4];

    auto ldgA = [&](int c) {
        const int k0 = c * KCH;
        #pragma unroll
        for (int i = 0; i < 4; i++)
            pa[i] = *(const float4*)(Abase + (size_t)(ar0 + i * 32) * NN + k0 + ac4);
    };
    auto stsA = [&](int c, int s) {
        const int k0 = c * KCH;
        #pragma unroll
        for (int i = 0; i < 4; i++) {
            int r = ar0 + i * 32;
            float4 v = pa[i];
            int diag = (row0 + r) - (k0 + ac4);
            if (diag >= 0 && diag < 4) ((float*)&v)[diag] += 1.0f;
            __half2 h0 = __floats2half2_rn(v.x, v.y);
            __half2 h1 = __floats2half2_rn(v.z, v.w);
            *(__half2*)(Asm[s] + r * A_STRIDE + ac4)     = h0;
            *(__half2*)(Asm[s] + r * A_STRIDE + ac4 + 2) = h1;
        }
    };
    auto cpB = [&](int c, int s) {
        const int k0 = c * KCH;
        #pragma unroll
        for (int i = 0; i < 2; i++) {
            int q  = tid + i * 256;
            int n  = q >> 2;            // 0..127 (f row)
            int k8 = (q & 3) * 8;       // 0,8,16,24 (halfs)
            cp16(smem_u32(Bsm[s] + n * B_STRIDE + k8),
                 Bbase + (size_t)n * NN + k0 + k8);
        }
    };

    float cacc[4][4][4];
    #pragma unroll
    for (int mi = 0; mi < 4; mi++)
        #pragma unroll
        for (int ni = 0; ni < 4; ni++)
            #pragma unroll
            for (int j = 0; j < 4; j++) cacc[mi][ni][j] = 0.f;

    // ---- prologue ----
    ldgA(0);
    cpB(0, 0);
    asm volatile("cp.async.commit_group;" ::: "memory");
    stsA(0, 0);
    ldgA(1);
    cpB(1, 1);
    asm volatile("cp.async.commit_group;" ::: "memory");
    asm volatile("cp.async.wait_group 1;" ::: "memory");   // B(0) landed
    __syncthreads();

    for (int c = 0; c < NCHUNK; c++) {
        const int s = c & 1;
        const __half* As = Asm[s];
        const __half* Bs = Bsm[s];

        #pragma unroll
        for (int ks = 0; ks < 2; ks++) {
            const int kk = ks * 16;          // halfs
            uint32_t a[4][4], bq[4][2];
            #pragma unroll
            for (int mi = 0; mi < 4; mi++) {
                int ar = wm * 64 + mi * 16 + lr;
                a[mi][0] = *(const uint32_t*)(As + ar * A_STRIDE + kk + 2 * lc);
                a[mi][1] = *(const uint32_t*)(As + (ar + 8) * A_STRIDE + kk + 2 * lc);
                a[mi][2] = *(const uint32_t*)(As + ar * A_STRIDE + kk + 2 * lc + 8);
                a[mi][3] = *(const uint32_t*)(As + (ar + 8) * A_STRIDE + kk + 2 * lc + 8);
            }
            #pragma unroll
            for (int ni = 0; ni < 4; ni++) {
                int bc = wn * 32 + ni * 8 + lr;
                bq[ni][0] = *(const uint32_t*)(Bs + bc * B_STRIDE + kk + 2 * lc);
                bq[ni][1] = *(const uint32_t*)(Bs + bc * B_STRIDE + kk + 2 * lc + 8);
            }
            #pragma unroll
            for (int mi = 0; mi < 4; mi++)
                #pragma unroll
                for (int ni = 0; ni < 4; ni++)
                    mma_f16(cacc[mi][ni], a[mi], bq[ni]);
        }

        if (c + 1 < NCHUNK) {
            __syncthreads();                 // all warps done reading stage s
            stsA(c + 1, s ^ 1);              // regs hold A(c+1)
            if (c + 2 < NCHUNK) {
                ldgA(c + 2);
                cpB(c + 2, s);
                asm volatile("cp.async.commit_group;" ::: "memory");
                asm volatile("cp.async.wait_group 1;" ::: "memory");  // B(c+1) done
            } else {
                asm volatile("cp.async.wait_group 0;" ::: "memory");
            }
            __syncthreads();
        }
    }

    // ---- epilogue: out = d[n]*acc + bias ----
    #pragma unroll
    for (int mi = 0; mi < 4; mi++) {
        #pragma unroll
        for (int ri = 0; ri < 2; ri++) {
            const int grow = row0 + wm * 64 + mi * 16 + lr + ri * 8;
            const float dn = g_d[batch * NN + grow];
            float* po = out + ((size_t)(batch * NN + grow)) * NF;
            #pragma unroll
            for (int ni = 0; ni < 4; ni++) {
                int f = wn * 32 + ni * 8 + 2 * lc;
                float2 bv = *(const float2*)(bias + f);
                float2 v;
                v.x = dn * cacc[mi][ni][ri * 2 + 0] + bv.x;
                v.y = dn * cacc[mi][ni][ri * 2 + 1] + bv.y;
                *(float2*)(po + f) = v;
            }
        }
    }
}

// ----------------------------------------------------------------
extern "C" void kernel_launch(void* const* d_in, const int* in_sizes, int n_in,
                              void* d_out, int out_size) {
    const float *x = nullptr, *adj = nullptr, *W = nullptr, *bias = nullptr;
    for (int i = 0; i < n_in; i++) {
        int s = in_sizes[i];
        if (s == NB * NN * NN)      adj  = (const float*)d_in[i];
        else if (s == NB * NN * NF) x    = (const float*)d_in[i];
        else if (s == NF * NF)      W    = (const float*)d_in[i];
        else if (s == NF)           bias = (const float*)d_in[i];
    }
    float* out = (float*)d_out;

    cudaFuncSetAttribute(adj_mma_kernel,
                         cudaFuncAttributeMaxDynamicSharedMemorySize, SMEM_BYTES);

    degree_kernel<<<NB * NN / 8, dim3(32, 8)>>>(adj);
    xw_kernel<<<NB * NN / 64, 256>>>(x, W);
    adj_mma_kernel<<<dim3(NN / 128, NB), 256, SMEM_BYTES>>>(adj, bias, out);
}

// round 6
// speedup vs baseline: 1.6751x; 1.3492x over previous
#include <cuda_runtime.h>
#include <cuda_fp16.h>
#include <cstdint>

#define NB 8
#define NN 2048
#define NF 128

// ---- scratch (device globals; no runtime allocation allowed) ----
__device__ float  g_d[NB * NN];                     // d^-1/2 per (b,n)
__device__ __half g_yt[(size_t)NB * NF * NN];       // fp16( d[m]*(xW^T)[m,f] ), [b][f][m]
__device__ __half g_adj16[(size_t)NB * NN * NN];    // fp16( adj + I ), 67 MB

// ----------------------------------------------------------------
__device__ __forceinline__ float to_tf32(float x) {
    uint32_t u;
    asm("cvt.rna.tf32.f32 %0, %1;" : "=r"(u) : "f"(x));
    return __uint_as_float(u);
}

__device__ __forceinline__ uint32_t smem_u32(const void* p) {
    uint32_t a;
    asm("{ .reg .u64 t; cvta.to.shared.u64 t, %1; cvt.u32.u64 %0, t; }"
        : "=r"(a) : "l"(p));
    return a;
}

__device__ __forceinline__ void mma_tf32(float* c, const uint32_t* a, const uint32_t* b) {
    asm volatile(
        "mma.sync.aligned.m16n8k8.row.col.f32.tf32.tf32.f32 "
        "{%0,%1,%2,%3},{%4,%5,%6,%7},{%8,%9},{%0,%1,%2,%3};"
        : "+f"(c[0]), "+f"(c[1]), "+f"(c[2]), "+f"(c[3])
        : "r"(a[0]), "r"(a[1]), "r"(a[2]), "r"(a[3]), "r"(b[0]), "r"(b[1]));
}

__device__ __forceinline__ void mma_f16(float* c, const uint32_t* a, const uint32_t* b) {
    asm volatile(
        "mma.sync.aligned.m16n8k16.row.col.f32.f16.f16.f32 "
        "{%0,%1,%2,%3},{%4,%5,%6,%7},{%8,%9},{%0,%1,%2,%3};"
        : "+f"(c[0]), "+f"(c[1]), "+f"(c[2]), "+f"(c[3])
        : "r"(a[0]), "r"(a[1]), "r"(a[2]), "r"(a[3]), "r"(b[0]), "r"(b[1]));
}

__device__ __forceinline__ void cp16(uint32_t dst, const void* src) {
    asm volatile("cp.async.cg.shared.global [%0], [%1], 16;"
                 :: "r"(dst), "l"(src) : "memory");
}

// ----------------------------------------------------------------
// Kernel 1: degree -> d^-1/2 AND fp16(adj + I) -> g_adj16.
// One warp per row of adj.
// ----------------------------------------------------------------
__global__ __launch_bounds__(256)
void degree_kernel(const float* __restrict__ adj) {
    int row  = blockIdx.x * 8 + threadIdx.y;   // 0 .. NB*NN-1
    int lane = threadIdx.x;
    int n    = row & (NN - 1);                 // row within batch (diag index)
    const float4* p = (const float4*)(adj + (size_t)row * NN);
    __half* q = g_adj16 + (size_t)row * NN;
    float s = 0.f;
    #pragma unroll 4
    for (int i = lane; i < NN / 4; i += 32) {
        float4 v = p[i];
        s += (v.x + v.y) + (v.z + v.w);
        int col = i * 4;
        int d = n - col;
        if (d >= 0 && d < 4) ((float*)&v)[d] += 1.0f;   // fold self-loop
        __half2 h0 = __floats2half2_rn(v.x, v.y);
        __half2 h1 = __floats2half2_rn(v.z, v.w);
        uint2 pk;
        pk.x = *(const uint32_t*)&h0;
        pk.y = *(const uint32_t*)&h1;
        *(uint2*)(q + col) = pk;
    }
    #pragma unroll
    for (int o = 16; o; o >>= 1) s += __shfl_xor_sync(0xFFFFFFFFu, s, o);
    if (lane == 0) g_d[row] = rsqrtf(s + 1.0f);
}

// ----------------------------------------------------------------
// Kernel 2: g_yt[b][f][m] = fp16( d[m] * sum_k x[m,k] * W[f,k] )
// CTA tile 64(m) x 128(f), tf32 MMA internally.
// ----------------------------------------------------------------
__global__ __launch_bounds__(256)
void xw_kernel(const float* __restrict__ x, const float* __restrict__ W) {
    __shared__ float As[64][36];
    __shared__ float Ws[128][36];

    const int tid  = threadIdx.x;
    const int lane = tid & 31;
    const int wid  = tid >> 5;
    const int wm   = wid >> 2;
    const int wn   = wid & 3;
    const int lr   = lane >> 2;
    const int lc   = lane & 3;
    const int m0   = blockIdx.x * 64;

    float cacc[2][4][4];
    #pragma unroll
    for (int mi = 0; mi < 2; mi++)
        #pragma unroll
        for (int ni = 0; ni < 4; ni++)
            #pragma unroll
            for (int j = 0; j < 4; j++) cacc[mi][ni][j] = 0.f;

    for (int kt = 0; kt < 4; ++kt) {
        const int k0 = kt * 32;
        #pragma unroll
        for (int i = 0; i < 2; i++) {
            int q = tid + i * 256;
            int r = q >> 3;
            int c4 = (q & 7) * 4;
            float4 v = *(const float4*)(x + (size_t)(m0 + r) * NF + k0 + c4);
            As[r][c4 + 0] = to_tf32(v.x);
            As[r][c4 + 1] = to_tf32(v.y);
            As[r][c4 + 2] = to_tf32(v.z);
            As[r][c4 + 3] = to_tf32(v.w);
        }
        #pragma unroll
        for (int i = 0; i < 4; i++) {
            int q = tid + i * 256;
            int r = q >> 3;
            int c4 = (q & 7) * 4;
            float4 v = *(const float4*)(W + (size_t)r * NF + k0 + c4);
            Ws[r][c4 + 0] = to_tf32(v.x);
            Ws[r][c4 + 1] = to_tf32(v.y);
            Ws[r][c4 + 2] = to_tf32(v.z);
            Ws[r][c4 + 3] = to_tf32(v.w);
        }
        __syncthreads();

        #pragma unroll
        for (int ks = 0; ks < 4; ks++) {
            const int kk = ks * 8;
            uint32_t a[2][4], bq[4][2];
            #pragma unroll
            for (int mi = 0; mi < 2; mi++) {
                int ar = wm * 32 + mi * 16 + lr;
                a[mi][0] = __float_as_uint(As[ar][kk + lc]);
                a[mi][1] = __float_as_uint(As[ar + 8][kk + lc]);
                a[mi][2] = __float_as_uint(As[ar][kk + lc + 4]);
                a[mi][3] = __float_as_uint(As[ar + 8][kk + lc + 4]);
            }
            #pragma unroll
            for (int ni = 0; ni < 4; ni++) {
                int bc = wn * 32 + ni * 8 + lr;
                bq[ni][0] = __float_as_uint(Ws[bc][kk + lc]);
                bq[ni][1] = __float_as_uint(Ws[bc][kk + lc + 4]);
            }
            #pragma unroll
            for (int mi = 0; mi < 2; mi++)
                #pragma unroll
                for (int ni = 0; ni < 4; ni++)
                    mma_tf32(cacc[mi][ni], a[mi], bq[ni]);
        }
        __syncthreads();
    }

    #pragma unroll
    for (int mi = 0; mi < 2; mi++) {
        #pragma unroll
        for (int ri = 0; ri < 2; ri++) {
            const int gm   = m0 + wm * 32 + mi * 16 + lr + ri * 8;
            const int b    = gm >> 11;
            const int mloc = gm & (NN - 1);
            const float dm = g_d[gm];
            #pragma unroll
            for (int ni = 0; ni < 4; ni++) {
                int f = wn * 32 + ni * 8 + 2 * lc;
                g_yt[(size_t)(b * NF + f)     * NN + mloc] =
                    __float2half_rn(dm * cacc[mi][ni][ri * 2 + 0]);
                g_yt[(size_t)(b * NF + f + 1) * NN + mloc] =
                    __float2half_rn(dm * cacc[mi][ni][ri * 2 + 1]);
            }
        }
    }
}

// ----------------------------------------------------------------
// Kernel 3: out[b,n,f] = d[n] * sum_m adj16[b,n,m] * yt[b,f,m] + bias[f]
// CTA 128(n) x 128(f), K=2048 in 32 chunks of 64.
// 512 threads, 16 warps (4x4), warp tile 32x32.
// 3-stage cp.async pipeline, both operands fp16 straight from gmem.
// ----------------------------------------------------------------
#define KCH2 64
#define NCH2 (NN / KCH2)       // 32
#define ASTR 72                // halfs per row (144B; conflict-free, 16B-aligned)
#define OP_HALFS (128 * ASTR)  // per operand per stage
#define STAGE_HALFS (2 * OP_HALFS)
#define SMEM_BYTES (3 * STAGE_HALFS * 2)   // 110592

__global__ __launch_bounds__(512, 1)
void adj_mma_kernel(const float* __restrict__ bias,
                    float* __restrict__ out) {
    extern __shared__ __half hsm[];

    const int tid  = threadIdx.x;
    const int lane = tid & 31;
    const int wid  = tid >> 5;
    const int wm   = wid >> 2;        // 0..3 over n (32 rows each)
    const int wn   = wid & 3;         // 0..3 over f (32 cols each)
    const int lr   = lane >> 2;       // 0..7
    const int lc   = lane & 3;        // 0..3
    const int row0  = blockIdx.x * 128;
    const int batch = blockIdx.y;

    const __half* Ag = g_adj16 + ((size_t)batch * NN + row0) * NN;
    const __half* Bg = g_yt + (size_t)batch * NF * NN;

    auto issue = [&](int c, int s) {
        __half* As = hsm + s * STAGE_HALFS;
        __half* Bs = As + OP_HALFS;
        const int k0 = c * KCH2;
        #pragma unroll
        for (int i = 0; i < 2; i++) {
            int q = tid + i * 512;
            int r = q >> 3;            // 0..127
            int o = (q & 7) * 8;       // halfs within 64-wide chunk
            cp16(smem_u32(As + r * ASTR + o), Ag + (size_t)r * NN + k0 + o);
            cp16(smem_u32(Bs + r * ASTR + o), Bg + (size_t)r * NN + k0 + o);
        }
        asm volatile("cp.async.commit_group;" ::: "memory");
    };

    float cacc[2][4][4];
    #pragma unroll
    for (int mi = 0; mi < 2; mi++)
        #pragma unroll
        for (int ni = 0; ni < 4; ni++)
            #pragma unroll
            for (int j = 0; j < 4; j++) cacc[mi][ni][j] = 0.f;

    issue(0, 0);
    issue(1, 1);

    for (int c = 0; c < NCH2; c++) {
        const int s = (c % 3);
        if (c < NCH2 - 1)
            asm volatile("cp.async.wait_group 1;" ::: "memory");
        else
            asm volatile("cp.async.wait_group 0;" ::: "memory");
        __syncthreads();

        const __half* As = hsm + s * STAGE_HALFS;
        const __half* Bs = As + OP_HALFS;

        #pragma unroll
        for (int ks = 0; ks < 4; ks++) {
            const int kk = ks * 16;
            uint32_t a[2][4], bq[4][2];
            #pragma unroll
            for (int mi = 0; mi < 2; mi++) {
                int ar = wm * 32 + mi * 16 + lr;
                a[mi][0] = *(const uint32_t*)(As + ar * ASTR + kk + 2 * lc);
                a[mi][1] = *(const uint32_t*)(As + (ar + 8) * ASTR + kk + 2 * lc);
                a[mi][2] = *(const uint32_t*)(As + ar * ASTR + kk + 2 * lc + 8);
                a[mi][3] = *(const uint32_t*)(As + (ar + 8) * ASTR + kk + 2 * lc + 8);
            }
            #pragma unroll
            for (int ni = 0; ni < 4; ni++) {
                int bc = wn * 32 + ni * 8 + lr;
                bq[ni][0] = *(const uint32_t*)(Bs + bc * ASTR + kk + 2 * lc);
                bq[ni][1] = *(const uint32_t*)(Bs + bc * ASTR + kk + 2 * lc + 8);
            }
            #pragma unroll
            for (int mi = 0; mi < 2; mi++)
                #pragma unroll
                for (int ni = 0; ni < 4; ni++)
                    mma_f16(cacc[mi][ni], a[mi], bq[ni]);
        }

        if (c + 2 < NCH2) issue(c + 2, (c + 2) % 3);
    }

    // ---- epilogue: out = d[n]*acc + bias ----
    #pragma unroll
    for (int mi = 0; mi < 2; mi++) {
        #pragma unroll
        for (int ri = 0; ri < 2; ri++) {
            const int grow = row0 + wm * 32 + mi * 16 + lr + ri * 8;
            const float dn = g_d[batch * NN + grow];
            float* po = out + ((size_t)(batch * NN + grow)) * NF;
            #pragma unroll
            for (int ni = 0; ni < 4; ni++) {
                int f = wn * 32 + ni * 8 + 2 * lc;
                float2 bv = *(const float2*)(bias + f);
                float2 v;
                v.x = dn * cacc[mi][ni][ri * 2 + 0] + bv.x;
                v.y = dn * cacc[mi][ni][ri * 2 + 1] + bv.y;
                *(float2*)(po + f) = v;
            }
        }
    }
}

// ----------------------------------------------------------------
extern "C" void kernel_launch(void* const* d_in, const int* in_sizes, int n_in,
                              void* d_out, int out_size) {
    const float *x = nullptr, *adj = nullptr, *W = nullptr, *bias = nullptr;
    for (int i = 0; i < n_in; i++) {
        int s = in_sizes[i];
        if (s == NB * NN * NN)      adj  = (const float*)d_in[i];
        else if (s == NB * NN * NF) x    = (const float*)d_in[i];
        else if (s == NF * NF)      W    = (const float*)d_in[i];
        else if (s == NF)           bias = (const float*)d_in[i];
    }
    float* out = (float*)d_out;

    cudaFuncSetAttribute(adj_mma_kernel,
                         cudaFuncAttributeMaxDynamicSharedMemorySize, SMEM_BYTES);

    degree_kernel<<<NB * NN / 8, dim3(32, 8)>>>(adj);
    xw_kernel<<<NB * NN / 64, 256>>>(x, W);
    adj_mma_kernel<<<dim3(NN / 128, NB), 512, SMEM_BYTES>>>(bias, out);
}

// round 7
// speedup vs baseline: 1.7562x; 1.0484x over previous
#include <cuda_runtime.h>
#include <cuda_fp16.h>
#include <cstdint>

#define NB 8
#define NN 2048
#define NF 128

// ---- scratch (device globals; no runtime allocation allowed) ----
__device__ float  g_d[NB * NN];                     // d^-1/2 per (b,n)
__device__ __half g_yt[(size_t)NB * NF * NN];       // fp16( d[m]*(xW^T)[m,f] ), [b][f][m]
__device__ __half g_adj16[(size_t)NB * NN * NN];    // fp16( adj + I ), 67 MB

// ----------------------------------------------------------------
__device__ __forceinline__ uint32_t smem_u32(const void* p) {
    uint32_t a;
    asm("{ .reg .u64 t; cvta.to.shared.u64 t, %1; cvt.u32.u64 %0, t; }"
        : "=r"(a) : "l"(p));
    return a;
}

__device__ __forceinline__ void mma_f16(float* c, const uint32_t* a, const uint32_t* b) {
    asm volatile(
        "mma.sync.aligned.m16n8k16.row.col.f32.f16.f16.f32 "
        "{%0,%1,%2,%3},{%4,%5,%6,%7},{%8,%9},{%0,%1,%2,%3};"
        : "+f"(c[0]), "+f"(c[1]), "+f"(c[2]), "+f"(c[3])
        : "r"(a[0]), "r"(a[1]), "r"(a[2]), "r"(a[3]), "r"(b[0]), "r"(b[1]));
}

__device__ __forceinline__ void ldsm_x4(uint32_t* r, uint32_t addr) {
    asm volatile("ldmatrix.sync.aligned.m8n8.x4.shared.b16 {%0,%1,%2,%3}, [%4];"
                 : "=r"(r[0]), "=r"(r[1]), "=r"(r[2]), "=r"(r[3]) : "r"(addr));
}

__device__ __forceinline__ void cp16(uint32_t dst, const void* src) {
    asm volatile("cp.async.cg.shared.global [%0], [%1], 16;"
                 :: "r"(dst), "l"(src) : "memory");
}

// ----------------------------------------------------------------
// Kernel 1: degree -> d^-1/2 AND fp16(adj + I) -> g_adj16.
// One warp per row of adj.  Streaming loads/stores (touch-once data).
// ----------------------------------------------------------------
__global__ __launch_bounds__(256)
void degree_kernel(const float* __restrict__ adj) {
    int row  = blockIdx.x * 8 + threadIdx.y;   // 0 .. NB*NN-1
    int lane = threadIdx.x;
    int n    = row & (NN - 1);                 // diag index within batch
    const float4* p = (const float4*)(adj + (size_t)row * NN);
    __half* q = g_adj16 + (size_t)row * NN;
    float s = 0.f;
    #pragma unroll 4
    for (int i = lane; i < NN / 4; i += 32) {
        float4 v = __ldcs(p + i);
        s += (v.x + v.y) + (v.z + v.w);
        int col = i * 4;
        int d = n - col;
        if (d >= 0 && d < 4) ((float*)&v)[d] += 1.0f;   // fold self-loop
        __half2 h0 = __floats2half2_rn(v.x, v.y);
        __half2 h1 = __floats2half2_rn(v.z, v.w);
        float2 pk;
        pk.x = __uint_as_float(*(const uint32_t*)&h0);
        pk.y = __uint_as_float(*(const uint32_t*)&h1);
        __stcs((float2*)(q + col), pk);
    }
    #pragma unroll
    for (int o = 16; o; o >>= 1) s += __shfl_xor_sync(0xFFFFFFFFu, s, o);
    if (lane == 0) g_d[row] = rsqrtf(s + 1.0f);
}

// ----------------------------------------------------------------
// Kernel 2 (fp16): g_yt[b][f][m] = fp16( d[m] * sum_k x[m,k] * W[f,k] )
// CTA tile 64(m) x 128(f), K=128 in 4 chunks of 32.
// 8 warps (wm 2 x wn 4), warp tile 32x32, m16n8k16.
// ----------------------------------------------------------------
__global__ __launch_bounds__(256)
void xw_kernel(const float* __restrict__ x, const float* __restrict__ W) {
    __shared__ __half As[64][40];
    __shared__ __half Ws[128][40];

    const int tid  = threadIdx.x;
    const int lane = tid & 31;
    const int wid  = tid >> 5;
    const int wm   = wid >> 2;        // 0..1 over m
    const int wn   = wid & 3;         // 0..3 over f
    const int lr   = lane >> 2;
    const int lc   = lane & 3;
    const int m0   = blockIdx.x * 64;

    float cacc[2][4][4];
    #pragma unroll
    for (int mi = 0; mi < 2; mi++)
        #pragma unroll
        for (int ni = 0; ni < 4; ni++)
            #pragma unroll
            for (int j = 0; j < 4; j++) cacc[mi][ni][j] = 0.f;

    for (int kt = 0; kt < 4; ++kt) {
        const int k0 = kt * 32;
        #pragma unroll
        for (int i = 0; i < 2; i++) {
            int q = tid + i * 256;
            int r = q >> 3;
            int c4 = (q & 7) * 4;
            float4 v = *(const float4*)(x + (size_t)(m0 + r) * NF + k0 + c4);
            *(__half2*)&As[r][c4]     = __floats2half2_rn(v.x, v.y);
            *(__half2*)&As[r][c4 + 2] = __floats2half2_rn(v.z, v.w);
        }
        #pragma unroll
        for (int i = 0; i < 4; i++) {
            int q = tid + i * 256;
            int r = q >> 3;
            int c4 = (q & 7) * 4;
            float4 v = *(const float4*)(W + (size_t)r * NF + k0 + c4);
            *(__half2*)&Ws[r][c4]     = __floats2half2_rn(v.x, v.y);
            *(__half2*)&Ws[r][c4 + 2] = __floats2half2_rn(v.z, v.w);
        }
        __syncthreads();

        #pragma unroll
        for (int ks = 0; ks < 2; ks++) {
            const int kk = ks * 16;
            uint32_t a[2][4], bq[4][2];
            #pragma unroll
            for (int mi = 0; mi < 2; mi++) {
                int ar = wm * 32 + mi * 16 + lr;
                a[mi][0] = *(const uint32_t*)(&As[ar][kk + 2 * lc]);
                a[mi][1] = *(const uint32_t*)(&As[ar + 8][kk + 2 * lc]);
                a[mi][2] = *(const uint32_t*)(&As[ar][kk + 2 * lc + 8]);
                a[mi][3] = *(const uint32_t*)(&As[ar + 8][kk + 2 * lc + 8]);
            }
            #pragma unroll
            for (int ni = 0; ni < 4; ni++) {
                int bc = wn * 32 + ni * 8 + lr;
                bq[ni][0] = *(const uint32_t*)(&Ws[bc][kk + 2 * lc]);
                bq[ni][1] = *(const uint32_t*)(&Ws[bc][kk + 2 * lc + 8]);
            }
            #pragma unroll
            for (int mi = 0; mi < 2; mi++)
                #pragma unroll
                for (int ni = 0; ni < 4; ni++)
                    mma_f16(cacc[mi][ni], a[mi], bq[ni]);
        }
        __syncthreads();
    }

    #pragma unroll
    for (int mi = 0; mi < 2; mi++) {
        #pragma unroll
        for (int ri = 0; ri < 2; ri++) {
            const int gm   = m0 + wm * 32 + mi * 16 + lr + ri * 8;
            const int b    = gm >> 11;
            const int mloc = gm & (NN - 1);
            const float dm = g_d[gm];
            #pragma unroll
            for (int ni = 0; ni < 4; ni++) {
                int f = wn * 32 + ni * 8 + 2 * lc;
                g_yt[(size_t)(b * NF + f)     * NN + mloc] =
                    __float2half_rn(dm * cacc[mi][ni][ri * 2 + 0]);
                g_yt[(size_t)(b * NF + f + 1) * NN + mloc] =
                    __float2half_rn(dm * cacc[mi][ni][ri * 2 + 1]);
            }
        }
    }
}

// ----------------------------------------------------------------
// Kernel 3: out[b,n,f] = d[n] * sum_m adj16[b,n,m] * yt[b,f,m] + bias[f]
// CTA 128(n) x 128(f), K=2048 in 32 chunks of 64.
// 512 threads, 16 warps (4x4), warp tile 32x32.
// 3-stage cp.async pipeline; fragments via ldmatrix.x4.
// ----------------------------------------------------------------
#define KCH2 64
#define NCH2 (NN / KCH2)       // 32
#define ASTR 72                // halfs per row (144B; conflict-free for LDSM)
#define OP_HALFS (128 * ASTR)
#define STAGE_HALFS (2 * OP_HALFS)
#define STAGE_BYTES (STAGE_HALFS * 2)
#define SMEM_BYTES (3 * STAGE_BYTES)   // 110592

__global__ __launch_bounds__(512, 1)
void adj_mma_kernel(const float* __restrict__ bias,
                    float* __restrict__ out) {
    extern __shared__ __half hsm[];
    const uint32_t hbase = smem_u32(hsm);

    const int tid  = threadIdx.x;
    const int lane = tid & 31;
    const int wid  = tid >> 5;
    const int wm   = wid >> 2;        // 0..3 over n (32 rows each)
    const int wn   = wid & 3;         // 0..3 over f (32 cols each)
    const int lr   = lane >> 2;
    const int lc   = lane & 3;
    const int row0  = blockIdx.x * 128;
    const int batch = blockIdx.y;

    const __half* Ag = g_adj16 + ((size_t)batch * NN + row0) * NN;
    const __half* Bg = g_yt + (size_t)batch * NF * NN;

    // ldmatrix lane->address offsets (bytes)
    const uint32_t aoff =
        (uint32_t)((wm * 32 + (lane & 7) + ((lane >> 3) & 1) * 8) * ASTR * 2
                   + ((lane >> 4) & 1) * 16);
    const uint32_t boff =
        (uint32_t)((wn * 32 + (lane & 7) + ((lane >> 4) & 1) * 8) * ASTR * 2
                   + ((lane >> 3) & 1) * 16);

    auto issue = [&](int c, int s) {
        __half* As = hsm + s * STAGE_HALFS;
        __half* Bs = As + OP_HALFS;
        const int k0 = c * KCH2;
        #pragma unroll
        for (int i = 0; i < 2; i++) {
            int q = tid + i * 512;
            int r = q >> 3;            // 0..127
            int o = (q & 7) * 8;       // halfs within 64-wide chunk
            cp16(smem_u32(As + r * ASTR + o), Ag + (size_t)r * NN + k0 + o);
            cp16(smem_u32(Bs + r * ASTR + o), Bg + (size_t)r * NN + k0 + o);
        }
        asm volatile("cp.async.commit_group;" ::: "memory");
    };

    float cacc[2][4][4];
    #pragma unroll
    for (int mi = 0; mi < 2; mi++)
        #pragma unroll
        for (int ni = 0; ni < 4; ni++)
            #pragma unroll
            for (int j = 0; j < 4; j++) cacc[mi][ni][j] = 0.f;

    issue(0, 0);
    issue(1, 1);

    for (int c = 0; c < NCH2; c++) {
        const int s = c % 3;
        if (c < NCH2 - 1)
            asm volatile("cp.async.wait_group 1;" ::: "memory");
        else
            asm volatile("cp.async.wait_group 0;" ::: "memory");
        __syncthreads();

        const uint32_t As_u = hbase + s * STAGE_BYTES;
        const uint32_t Bs_u = As_u + OP_HALFS * 2;

        #pragma unroll
        for (int ks = 0; ks < 4; ks++) {
            const uint32_t kb = ks * 32;          // bytes (16 halfs)
            uint32_t a[2][4], bt[2][4];
            ldsm_x4(a[0], As_u + aoff + kb);
            ldsm_x4(a[1], As_u + aoff + 16 * ASTR * 2 + kb);
            ldsm_x4(bt[0], Bs_u + boff + kb);
            ldsm_x4(bt[1], Bs_u + boff + 16 * ASTR * 2 + kb);
            // bt[p] = { b[2p][0], b[2p][1], b[2p+1][0], b[2p+1][1] }
            #pragma unroll
            for (int mi = 0; mi < 2; mi++)
                #pragma unroll
                for (int ni = 0; ni < 4; ni++)
                    mma_f16(cacc[mi][ni], a[mi], &bt[ni >> 1][(ni & 1) * 2]);
        }

        if (c + 2 < NCH2) issue(c + 2, (c + 2) % 3);
    }

    // ---- epilogue: out = d[n]*acc + bias ----
    #pragma unroll
    for (int mi = 0; mi < 2; mi++) {
        #pragma unroll
        for (int ri = 0; ri < 2; ri++) {
            const int grow = row0 + wm * 32 + mi * 16 + lr + ri * 8;
            const float dn = g_d[batch * NN + grow];
            float* po = out + ((size_t)(batch * NN + grow)) * NF;
            #pragma unroll
            for (int ni = 0; ni < 4; ni++) {
                int f = wn * 32 + ni * 8 + 2 * lc;
                float2 bv = *(const float2*)(bias + f);
                float2 v;
                v.x = dn * cacc[mi][ni][ri * 2 + 0] + bv.x;
                v.y = dn * cacc[mi][ni][ri * 2 + 1] + bv.y;
                *(float2*)(po + f) = v;
            }
        }
    }
}

// ----------------------------------------------------------------
extern "C" void kernel_launch(void* const* d_in, const int* in_sizes, int n_in,
                              void* d_out, int out_size) {
    const float *x = nullptr, *adj = nullptr, *W = nullptr, *bias = nullptr;
    for (int i = 0; i < n_in; i++) {
        int s = in_sizes[i];
        if (s == NB * NN * NN)      adj  = (const float*)d_in[i];
        else if (s == NB * NN * NF) x    = (const float*)d_in[i];
        else if (s == NF * NF)      W    = (const float*)d_in[i];
        else if (s == NF)           bias = (const float*)d_in[i];
    }
    float* out = (float*)d_out;

    cudaFuncSetAttribute(adj_mma_kernel,
                         cudaFuncAttributeMaxDynamicSharedMemorySize, SMEM_BYTES);

    degree_kernel<<<NB * NN / 8, dim3(32, 8)>>>(adj);
    xw_kernel<<<NB * NN / 64, 256>>>(x, W);
    adj_mma_kernel<<<dim3(NN / 128, NB), 512, SMEM_BYTES>>>(bias, out);
}

// round 8
// speedup vs baseline: 1.8470x; 1.0517x over previous
#include <cuda_runtime.h>
#include <cuda_fp16.h>
#include <cstdint>

#define NB 8
#define NN 2048
#define NF 128

// ---- scratch (device globals; no runtime allocation allowed) ----
__device__ float  g_d[NB * NN];                     // d^-1/2 per (b,n)
__device__ __half g_yt[(size_t)NB * NF * NN];       // fp16( d[m]*(xW^T)[m,f] ), [b][f][m]
__device__ __half g_adj16[(size_t)NB * NN * NN];    // fp16( adj + I ), 67 MB

// ----------------------------------------------------------------
__device__ __forceinline__ uint32_t smem_u32(const void* p) {
    uint32_t a;
    asm("{ .reg .u64 t; cvta.to.shared.u64 t, %1; cvt.u32.u64 %0, t; }"
        : "=r"(a) : "l"(p));
    return a;
}

__device__ __forceinline__ void mma_f16(float* c, const uint32_t* a, const uint32_t* b) {
    asm volatile(
        "mma.sync.aligned.m16n8k16.row.col.f32.f16.f16.f32 "
        "{%0,%1,%2,%3},{%4,%5,%6,%7},{%8,%9},{%0,%1,%2,%3};"
        : "+f"(c[0]), "+f"(c[1]), "+f"(c[2]), "+f"(c[3])
        : "r"(a[0]), "r"(a[1]), "r"(a[2]), "r"(a[3]), "r"(b[0]), "r"(b[1]));
}

__device__ __forceinline__ void ldsm_x4(uint32_t* r, uint32_t addr) {
    asm volatile("ldmatrix.sync.aligned.m8n8.x4.shared.b16 {%0,%1,%2,%3}, [%4];"
                 : "=r"(r[0]), "=r"(r[1]), "=r"(r[2]), "=r"(r[3]) : "r"(addr));
}

__device__ __forceinline__ void cp16(uint32_t dst, const void* src) {
    asm volatile("cp.async.cg.shared.global [%0], [%1], 16;"
                 :: "r"(dst), "l"(src) : "memory");
}

// ----------------------------------------------------------------
// Kernel 1: degree -> d^-1/2 AND fp16(adj + I) -> g_adj16.
// One warp per row; 32B in / 16B out per lane-iteration (STG.128).
// ----------------------------------------------------------------
__global__ __launch_bounds__(256)
void degree_kernel(const float* __restrict__ adj) {
    int row  = blockIdx.x * 8 + threadIdx.y;   // 0 .. NB*NN-1
    int lane = threadIdx.x;
    int n    = row & (NN - 1);                 // diag index within batch
    const float4* p = (const float4*)(adj + (size_t)row * NN);
    __half* q = g_adj16 + (size_t)row * NN;
    float s = 0.f;
    #pragma unroll
    for (int i = lane; i < NN / 8; i += 32) {  // 8 iterations
        float4 v0 = __ldcs(p + 2 * i);
        float4 v1 = __ldcs(p + 2 * i + 1);
        s += ((v0.x + v0.y) + (v0.z + v0.w)) + ((v1.x + v1.y) + (v1.z + v1.w));
        int col = i * 8;
        int d = n - col;
        if (d >= 0 && d < 8) {                 // fold self-loop
            if (d < 4) ((float*)&v0)[d] += 1.0f;
            else       ((float*)&v1)[d - 4] += 1.0f;
        }
        __half2 h0 = __floats2half2_rn(v0.x, v0.y);
        __half2 h1 = __floats2half2_rn(v0.z, v0.w);
        __half2 h2 = __floats2half2_rn(v1.x, v1.y);
        __half2 h3 = __floats2half2_rn(v1.z, v1.w);
        float4 pk;
        pk.x = __uint_as_float(*(const uint32_t*)&h0);
        pk.y = __uint_as_float(*(const uint32_t*)&h1);
        pk.z = __uint_as_float(*(const uint32_t*)&h2);
        pk.w = __uint_as_float(*(const uint32_t*)&h3);
        __stcs((float4*)(q + col), pk);
    }
    #pragma unroll
    for (int o = 16; o; o >>= 1) s += __shfl_xor_sync(0xFFFFFFFFu, s, o);
    if (lane == 0) g_d[row] = rsqrtf(s + 1.0f);
}

// ----------------------------------------------------------------
// Kernel 2 (fp16): g_yt[b][f][m] = fp16( d[m] * sum_k x[m,k] * W[f,k] )
// CTA tile 64(m) x 128(f), K=128 in 4 chunks of 32, m16n8k16.
// ----------------------------------------------------------------
__global__ __launch_bounds__(256)
void xw_kernel(const float* __restrict__ x, const float* __restrict__ W) {
    __shared__ __half As[64][40];
    __shared__ __half Ws[128][40];

    const int tid  = threadIdx.x;
    const int lane = tid & 31;
    const int wid  = tid >> 5;
    const int wm   = wid >> 2;        // 0..1 over m
    const int wn   = wid & 3;         // 0..3 over f
    const int lr   = lane >> 2;
    const int lc   = lane & 3;
    const int m0   = blockIdx.x * 64;

    float cacc[2][4][4];
    #pragma unroll
    for (int mi = 0; mi < 2; mi++)
        #pragma unroll
        for (int ni = 0; ni < 4; ni++)
            #pragma unroll
            for (int j = 0; j < 4; j++) cacc[mi][ni][j] = 0.f;

    for (int kt = 0; kt < 4; ++kt) {
        const int k0 = kt * 32;
        #pragma unroll
        for (int i = 0; i < 2; i++) {
            int q = tid + i * 256;
            int r = q >> 3;
            int c4 = (q & 7) * 4;
            float4 v = *(const float4*)(x + (size_t)(m0 + r) * NF + k0 + c4);
            *(__half2*)&As[r][c4]     = __floats2half2_rn(v.x, v.y);
            *(__half2*)&As[r][c4 + 2] = __floats2half2_rn(v.z, v.w);
        }
        #pragma unroll
        for (int i = 0; i < 4; i++) {
            int q = tid + i * 256;
            int r = q >> 3;
            int c4 = (q & 7) * 4;
            float4 v = *(const float4*)(W + (size_t)r * NF + k0 + c4);
            *(__half2*)&Ws[r][c4]     = __floats2half2_rn(v.x, v.y);
            *(__half2*)&Ws[r][c4 + 2] = __floats2half2_rn(v.z, v.w);
        }
        __syncthreads();

        #pragma unroll
        for (int ks = 0; ks < 2; ks++) {
            const int kk = ks * 16;
            uint32_t a[2][4], bq[4][2];
            #pragma unroll
            for (int mi = 0; mi < 2; mi++) {
                int ar = wm * 32 + mi * 16 + lr;
                a[mi][0] = *(const uint32_t*)(&As[ar][kk + 2 * lc]);
                a[mi][1] = *(const uint32_t*)(&As[ar + 8][kk + 2 * lc]);
                a[mi][2] = *(const uint32_t*)(&As[ar][kk + 2 * lc + 8]);
                a[mi][3] = *(const uint32_t*)(&As[ar + 8][kk + 2 * lc + 8]);
            }
            #pragma unroll
            for (int ni = 0; ni < 4; ni++) {
                int bc = wn * 32 + ni * 8 + lr;
                bq[ni][0] = *(const uint32_t*)(&Ws[bc][kk + 2 * lc]);
                bq[ni][1] = *(const uint32_t*)(&Ws[bc][kk + 2 * lc + 8]);
            }
            #pragma unroll
            for (int mi = 0; mi < 2; mi++)
                #pragma unroll
                for (int ni = 0; ni < 4; ni++)
                    mma_f16(cacc[mi][ni], a[mi], bq[ni]);
        }
        __syncthreads();
    }

    #pragma unroll
    for (int mi = 0; mi < 2; mi++) {
        #pragma unroll
        for (int ri = 0; ri < 2; ri++) {
            const int gm   = m0 + wm * 32 + mi * 16 + lr + ri * 8;
            const int b    = gm >> 11;
            const int mloc = gm & (NN - 1);
            const float dm = g_d[gm];
            #pragma unroll
            for (int ni = 0; ni < 4; ni++) {
                int f = wn * 32 + ni * 8 + 2 * lc;
                g_yt[(size_t)(b * NF + f)     * NN + mloc] =
                    __float2half_rn(dm * cacc[mi][ni][ri * 2 + 0]);
                g_yt[(size_t)(b * NF + f + 1) * NN + mloc] =
                    __float2half_rn(dm * cacc[mi][ni][ri * 2 + 1]);
            }
        }
    }
}

// ----------------------------------------------------------------
// Kernel 3: out[b,n,f] = d[n] * sum_m adj16[b,n,m] * yt[b,f,m] + bias[f]
// CTA 64(n) x 128(f), K=2048 in 32 chunks of 64.
// 256 threads, 8 warps (2x4), warp tile 32x32, 2 CTAs/SM.
// 3-stage cp.async pipeline; fragments via ldmatrix.x4.
// ----------------------------------------------------------------
#define KCH2 64
#define NCH2 (NN / KCH2)       // 32
#define ASTR 72                // halfs per row (144B; conflict-free for LDSM)
#define A_HALFS (64 * ASTR)
#define B_HALFS (128 * ASTR)
#define STAGE_HALFS (A_HALFS + B_HALFS)
#define STAGE_BYTES (STAGE_HALFS * 2)      // 27648
#define SMEM_BYTES (3 * STAGE_BYTES)       // 82944

__global__ __launch_bounds__(256, 2)
void adj_mma_kernel(const float* __restrict__ bias,
                    float* __restrict__ out) {
    extern __shared__ __half hsm[];
    const uint32_t hbase = smem_u32(hsm);

    const int tid  = threadIdx.x;
    const int lane = tid & 31;
    const int wid  = tid >> 5;
    const int wm   = wid >> 2;        // 0..1 over n (32 rows each)
    const int wn   = wid & 3;         // 0..3 over f (32 cols each)
    const int lr   = lane >> 2;
    const int lc   = lane & 3;
    const int row0  = blockIdx.x * 64;
    const int batch = blockIdx.y;

    const __half* Ag = g_adj16 + ((size_t)batch * NN + row0) * NN;
    const __half* Bg = g_yt + (size_t)batch * NF * NN;

    // ldmatrix lane->address offsets (bytes)
    const uint32_t aoff =
        (uint32_t)((wm * 32 + (lane & 7) + ((lane >> 3) & 1) * 8) * ASTR * 2
                   + ((lane >> 4) & 1) * 16);
    const uint32_t boff =
        (uint32_t)((wn * 32 + (lane & 7) + ((lane >> 4) & 1) * 8) * ASTR * 2
                   + ((lane >> 3) & 1) * 16);

    auto issue = [&](int c, int s) {
        __half* As = hsm + s * STAGE_HALFS;
        __half* Bs = As + A_HALFS;
        const int k0 = c * KCH2;
        #pragma unroll
        for (int i = 0; i < 2; i++) {           // A: 64 rows x 64 halfs
            int q = tid + i * 256;
            int r = q >> 3;
            int o = (q & 7) * 8;
            cp16(smem_u32(As + r * ASTR + o), Ag + (size_t)r * NN + k0 + o);
        }
        #pragma unroll
        for (int i = 0; i < 4; i++) {           // B: 128 rows x 64 halfs
            int q = tid + i * 256;
            int r = q >> 3;
            int o = (q & 7) * 8;
            cp16(smem_u32(Bs + r * ASTR + o), Bg + (size_t)r * NN + k0 + o);
        }
        asm volatile("cp.async.commit_group;" ::: "memory");
    };

    float cacc[2][4][4];
    #pragma unroll
    for (int mi = 0; mi < 2; mi++)
        #pragma unroll
        for (int ni = 0; ni < 4; ni++)
            #pragma unroll
            for (int j = 0; j < 4; j++) cacc[mi][ni][j] = 0.f;

    issue(0, 0);
    issue(1, 1);

    for (int c = 0; c < NCH2; c++) {
        const int s = c % 3;
        if (c < NCH2 - 1)
            asm volatile("cp.async.wait_group 1;" ::: "memory");
        else
            asm volatile("cp.async.wait_group 0;" ::: "memory");
        __syncthreads();

        const uint32_t As_u = hbase + s * STAGE_BYTES;
        const uint32_t Bs_u = As_u + A_HALFS * 2;

        #pragma unroll
        for (int ks = 0; ks < 4; ks++) {
            const uint32_t kb = ks * 32;          // bytes (16 halfs)
            uint32_t a[2][4], bt[2][4];
            ldsm_x4(a[0], As_u + aoff + kb);
            ldsm_x4(a[1], As_u + aoff + 16 * ASTR * 2 + kb);
            ldsm_x4(bt[0], Bs_u + boff + kb);
            ldsm_x4(bt[1], Bs_u + boff + 16 * ASTR * 2 + kb);
            #pragma unroll
            for (int mi = 0; mi < 2; mi++)
                #pragma unroll
                for (int ni = 0; ni < 4; ni++)
                    mma_f16(cacc[mi][ni], a[mi], &bt[ni >> 1][(ni & 1) * 2]);
        }

        if (c + 2 < NCH2) issue(c + 2, (c + 2) % 3);
    }

    // ---- epilogue: out = d[n]*acc + bias ----
    #pragma unroll
    for (int mi = 0; mi < 2; mi++) {
        #pragma unroll
        for (int ri = 0; ri < 2; ri++) {
            const int grow = row0 + wm * 32 + mi * 16 + lr + ri * 8;
            const float dn = g_d[batch * NN + grow];
            float* po = out + ((size_t)(batch * NN + grow)) * NF;
            #pragma unroll
            for (int ni = 0; ni < 4; ni++) {
                int f = wn * 32 + ni * 8 + 2 * lc;
                float2 bv = *(const float2*)(bias + f);
                float2 v;
                v.x = dn * cacc[mi][ni][ri * 2 + 0] + bv.x;
                v.y = dn * cacc[mi][ni][ri * 2 + 1] + bv.y;
                *(float2*)(po + f) = v;
            }
        }
    }
}

// ----------------------------------------------------------------
extern "C" void kernel_launch(void* const* d_in, const int* in_sizes, int n_in,
                              void* d_out, int out_size) {
    const float *x = nullptr, *adj = nullptr, *W = nullptr, *bias = nullptr;
    for (int i = 0; i < n_in; i++) {
        int s = in_sizes[i];
        if (s == NB * NN * NN)      adj  = (const float*)d_in[i];
        else if (s == NB * NN * NF) x    = (const float*)d_in[i];
        else if (s == NF * NF)      W    = (const float*)d_in[i];
        else if (s == NF)           bias = (const float*)d_in[i];
    }
    float* out = (float*)d_out;

    cudaFuncSetAttribute(adj_mma_kernel,
                         cudaFuncAttributeMaxDynamicSharedMemorySize, SMEM_BYTES);

    degree_kernel<<<NB * NN / 8, dim3(32, 8)>>>(adj);
    xw_kernel<<<NB * NN / 64, 256>>>(x, W);
    adj_mma_kernel<<<dim3(NN / 64, NB), 256, SMEM_BYTES>>>(bias, out);
}